// round 4
// baseline (speedup 1.0000x reference)
#include <cuda_runtime.h>

#define HID 64
#define MAXN 500000
#define MAXE 800000

typedef unsigned long long ull;

__device__ __forceinline__ ull pack2(float lo, float hi) {
    ull r; asm("mov.b64 %0, {%1,%2};" : "=l"(r) : "f"(lo), "f"(hi)); return r;
}
__device__ __forceinline__ void unpack2(ull v, float& lo, float& hi) {
    asm("mov.b64 {%0,%1}, %2;" : "=f"(lo), "=f"(hi) : "l"(v));
}
__device__ __forceinline__ void fma2(ull& d, ull a, ull b) {
    asm("fma.rn.f32x2 %0, %1, %2, %0;" : "+l"(d) : "l"(a), "l"(b));
}

// ---------------- scratch (device globals; allocation-free rule) ----------------
__device__ float g_h[50000 * HID];
__device__ float g_e[500000 * HID];
__device__ float g_l[800000 * HID];
__device__ float g_A[MAXN * HID];
__device__ float g_B[MAXN * HID];
__device__ float g_D[MAXN * HID];
__device__ float g_E[MAXN * HID];
__device__ float g_C[MAXE * HID];      // Ce = e @ W2 + b2
__device__ float g_accsh[MAXN * HID];
__device__ float g_accs[MAXN * HID];
__device__ int   g_off[2048];

// ---------------- misc kernels ----------------

__global__ void embed_kernel(const int* __restrict__ an,
                             const float* __restrict__ emb, int n) {
    int i = blockIdx.x * blockDim.x + threadIdx.x;
    if (i < n * HID) g_h[i] = emb[an[i >> 6] * HID + (i & 63)];
}

__global__ void rbf_kernel(const float* __restrict__ x, const float* __restrict__ W,
                           const float* __restrict__ bias, float* __restrict__ out,
                           int n, int bins, float vmin, float step, float gamma) {
    __shared__ float phi[8 * 80];
    __shared__ float xs[8];
    int tx = threadIdx.x & 31, ez = threadIdx.x >> 5;
    ull bp = *(const ull*)(bias + 2 * tx);
    for (int base = blockIdx.x * 8; base < n; base += gridDim.x * 8) {
        __syncthreads();
        if (threadIdx.x < 8)
            xs[threadIdx.x] = (base + threadIdx.x < n) ? x[base + threadIdx.x] : 0.f;
        __syncthreads();
        for (int idx = threadIdx.x; idx < 8 * bins; idx += 256) {
            int ee = idx / bins, k = idx - ee * bins;
            float dd = xs[ee] - (vmin + k * step);
            phi[idx] = __expf(-gamma * dd * dd);
        }
        __syncthreads();
        int eid = base + ez;
        if (eid < n) {
            ull acc = bp;
            for (int k = 0; k < bins; k++) {
                float p = phi[ez * bins + k];
                fma2(acc, pack2(p, p), __ldg((const ull*)(W + k * HID + 2 * tx)));
            }
            *(ull*)(out + (size_t)eid * HID + 2 * tx) = acc;
        }
    }
}

// ---------------- GEMM kernels (row-pair packed FFMA2) ----------------

// A,B,D,E = h @ {W0,W1,W3,W4} + bias; also zeroes g_accsh/g_accs rows.
// Tile = 128 rows. Warp handles 8 row-pairs (16 rows), output split tx / tx+32.
// Dynamic smem: Ws[4*4096] floats (64KB) + xsi[64*64] ull (32KB) = 96KB.
__global__ void __launch_bounds__(256, 2) gemm4_kernel(
    const float* __restrict__ h, const float* __restrict__ W,
    const float* __restrict__ bias, int n) {
    extern __shared__ __align__(16) float smem[];
    float* Ws = smem;                       // 4 * 4096 floats
    ull* xsi = (ull*)(smem + 4 * 4096);     // 64 pairs * 64 k
    int tx = threadIdx.x & 31, wz = threadIdx.x >> 5;
    const int msel0 = 0, msel1 = 1, msel2 = 3, msel3 = 4;
    for (int i = threadIdx.x; i < 4096; i += 256) {
        Ws[0 * 4096 + i] = W[msel0 * 4096 + i];
        Ws[1 * 4096 + i] = W[msel1 * 4096 + i];
        Ws[2 * 4096 + i] = W[msel2 * 4096 + i];
        Ws[3 * 4096 + i] = W[msel3 * 4096 + i];
    }
    float bb[4][2];
    bb[0][0] = bias[msel0 * 64 + tx]; bb[0][1] = bias[msel0 * 64 + tx + 32];
    bb[1][0] = bias[msel1 * 64 + tx]; bb[1][1] = bias[msel1 * 64 + tx + 32];
    bb[2][0] = bias[msel2 * 64 + tx]; bb[2][1] = bias[msel2 * 64 + tx + 32];
    bb[3][0] = bias[msel3 * 64 + tx]; bb[3][1] = bias[msel3 * 64 + tx + 32];

    for (int base = blockIdx.x * 128; base < n; base += gridDim.x * 128) {
        __syncthreads();
        // stage interleaved row-pairs
        for (int t = threadIdx.x; t < 1024; t += 256) {
            int p = t >> 4, k4 = t & 15;
            int r0 = base + 2 * p, r1 = r0 + 1;
            float4 a = make_float4(0.f, 0.f, 0.f, 0.f), b = a;
            if (r0 < n) a = *(const float4*)(h + (size_t)r0 * 64 + k4 * 4);
            if (r1 < n) b = *(const float4*)(h + (size_t)r1 * 64 + k4 * 4);
            ull* dst = xsi + p * 64 + k4 * 4;
            dst[0] = pack2(a.x, b.x); dst[1] = pack2(a.y, b.y);
            dst[2] = pack2(a.z, b.z); dst[3] = pack2(a.w, b.w);
        }
        // zero segment accumulators for this tile
        {
            float4 z = make_float4(0.f, 0.f, 0.f, 0.f);
            for (int t = threadIdx.x; t < 128 * 16; t += 256) {
                int r = base + (t >> 4);
                if (r < n) {
                    size_t o = (size_t)r * 64 + (t & 15) * 4;
                    *(float4*)(g_accsh + o) = z;
                    *(float4*)(g_accs + o)  = z;
                }
            }
        }
        __syncthreads();
        int p0 = wz * 8;
#pragma unroll
        for (int pass = 0; pass < 2; pass++) {
            const float* Wa = Ws + (2 * pass) * 4096;
            const float* Wb = Ws + (2 * pass + 1) * 4096;
            ull acc[2][2][8];
#pragma unroll
            for (int p = 0; p < 8; p++) {
                acc[0][0][p] = pack2(bb[2 * pass][0], bb[2 * pass][0]);
                acc[0][1][p] = pack2(bb[2 * pass][1], bb[2 * pass][1]);
                acc[1][0][p] = pack2(bb[2 * pass + 1][0], bb[2 * pass + 1][0]);
                acc[1][1][p] = pack2(bb[2 * pass + 1][1], bb[2 * pass + 1][1]);
            }
#pragma unroll 8
            for (int k = 0; k < 64; k++) {
                float wa0 = Wa[k * 64 + tx], wa1 = Wa[k * 64 + tx + 32];
                float wb0 = Wb[k * 64 + tx], wb1 = Wb[k * 64 + tx + 32];
                ull wda0 = pack2(wa0, wa0), wda1 = pack2(wa1, wa1);
                ull wdb0 = pack2(wb0, wb0), wdb1 = pack2(wb1, wb1);
#pragma unroll
                for (int p = 0; p < 8; p++) {
                    ull xb = xsi[(p0 + p) * 64 + k];
                    fma2(acc[0][0][p], xb, wda0);
                    fma2(acc[0][1][p], xb, wda1);
                    fma2(acc[1][0][p], xb, wdb0);
                    fma2(acc[1][1][p], xb, wdb1);
                }
            }
            float* buf0 = (pass == 0) ? g_A : g_D;
            float* buf1 = (pass == 0) ? g_B : g_E;
#pragma unroll
            for (int p = 0; p < 8; p++) {
                int r0 = base + 2 * (p0 + p), r1 = r0 + 1;
#pragma unroll
                for (int jh = 0; jh < 2; jh++) {
                    float l0, h0, l1, h1;
                    unpack2(acc[0][jh][p], l0, h0);
                    unpack2(acc[1][jh][p], l1, h1);
                    int col = tx + 32 * jh;
                    if (r0 < n) {
                        buf0[(size_t)r0 * 64 + col] = l0;
                        buf1[(size_t)r0 * 64 + col] = l1;
                    }
                    if (r1 < n) {
                        buf0[(size_t)r1 * 64 + col] = h0;
                        buf1[(size_t)r1 * 64 + col] = h1;
                    }
                }
            }
        }
    }
}

// Ce = x @ W2 + b2. Tile = 256 rows; warp handles 16 row-pairs.
// Dynamic smem: Ws[4096] floats (16KB) + xsi[128*64] ull (64KB) = 80KB.
__global__ void __launch_bounds__(256, 2) gemm1_kernel(
    const float* __restrict__ x, const float* __restrict__ W2,
    const float* __restrict__ b2, float* __restrict__ out, int n) {
    extern __shared__ __align__(16) float smem[];
    float* Ws = smem;                   // 4096 floats
    ull* xsi = (ull*)(smem + 4096);     // 128 pairs * 64 k
    int tx = threadIdx.x & 31, wz = threadIdx.x >> 5;
    for (int i = threadIdx.x; i < 4096; i += 256) Ws[i] = W2[i];
    float b0 = b2[tx], b1 = b2[tx + 32];

    for (int base = blockIdx.x * 256; base < n; base += gridDim.x * 256) {
        __syncthreads();
        for (int t = threadIdx.x; t < 2048; t += 256) {
            int p = t >> 4, k4 = t & 15;
            int r0 = base + 2 * p, r1 = r0 + 1;
            float4 a = make_float4(0.f, 0.f, 0.f, 0.f), b = a;
            if (r0 < n) a = *(const float4*)(x + (size_t)r0 * 64 + k4 * 4);
            if (r1 < n) b = *(const float4*)(x + (size_t)r1 * 64 + k4 * 4);
            ull* dst = xsi + p * 64 + k4 * 4;
            dst[0] = pack2(a.x, b.x); dst[1] = pack2(a.y, b.y);
            dst[2] = pack2(a.z, b.z); dst[3] = pack2(a.w, b.w);
        }
        __syncthreads();
        int p0 = wz * 16;
        ull acc[2][16];
#pragma unroll
        for (int p = 0; p < 16; p++) {
            acc[0][p] = pack2(b0, b0);
            acc[1][p] = pack2(b1, b1);
        }
#pragma unroll 8
        for (int k = 0; k < 64; k++) {
            float w0 = Ws[k * 64 + tx], w1 = Ws[k * 64 + tx + 32];
            ull wd0 = pack2(w0, w0), wd1 = pack2(w1, w1);
#pragma unroll
            for (int p = 0; p < 16; p++) {
                ull xb = xsi[(p0 + p) * 64 + k];
                fma2(acc[0][p], xb, wd0);
                fma2(acc[1][p], xb, wd1);
            }
        }
#pragma unroll
        for (int p = 0; p < 16; p++) {
            int r0 = base + 2 * (p0 + p), r1 = r0 + 1;
#pragma unroll
            for (int jh = 0; jh < 2; jh++) {
                float lo, hi;
                unpack2(acc[jh][p], lo, hi);
                int col = tx + 32 * jh;
                if (r0 < n) out[(size_t)r0 * 64 + col] = lo;
                if (r1 < n) out[(size_t)r1 * 64 + col] = hi;
            }
        }
    }
}

// ---------------- gather / scatter kernels ----------------

// Per edge: e_new = D[src]+E[dst]+Ce; sigma; atomic segment sums; optional e += silu.
__global__ void edge2_kernel(const int* __restrict__ src, const int* __restrict__ dst,
                             float* __restrict__ e, int E, int write_e) {
    int tx = threadIdx.x & 31;
    int gw = (blockIdx.x * blockDim.x + threadIdx.x) >> 5;
    int nw = (gridDim.x * blockDim.x) >> 5;
    for (int eid = gw; eid < E; eid += nw) {
        int s = __ldg(src + eid);
        int d = __ldg(dst + eid);
        size_t eo = (size_t)eid * 64 + 2 * tx;
        size_t so = (size_t)s * 64 + 2 * tx;
        size_t dofs = (size_t)d * 64 + 2 * tx;
        float2 ce = __ldg((const float2*)(g_C + eo));
        float2 dh = __ldg((const float2*)(g_D + so));
        float2 eh = __ldg((const float2*)(g_E + dofs));
        float2 bh = __ldg((const float2*)(g_B + so));
        float en0 = dh.x + eh.x + ce.x;
        float en1 = dh.y + eh.y + ce.y;
        float sg0 = 1.f / (1.f + __expf(-en0));
        float sg1 = 1.f / (1.f + __expf(-en1));
        atomicAdd(g_accsh + dofs,     bh.x * sg0);
        atomicAdd(g_accsh + dofs + 1, bh.y * sg1);
        atomicAdd(g_accs + dofs,      sg0);
        atomicAdd(g_accs + dofs + 1,  sg1);
        if (write_e) {
            float2 ev = *(const float2*)(e + eo);
            ev.x += en0 * sg0;
            ev.y += en1 * sg1;
            *(float2*)(e + eo) = ev;
        }
    }
}

__global__ void node_kernel(float* __restrict__ h, int n) {
    int i = blockIdx.x * blockDim.x + threadIdx.x;
    if (i < n * HID) {
        float hn = g_A[i] + g_accsh[i] / (g_accs[i] + 1e-6f);
        h[i] += hn / (1.f + __expf(-hn));
    }
}

__global__ void offsets_kernel(const int* __restrict__ len, int Bc) {
    if (threadIdx.x == 0 && blockIdx.x == 0) {
        int o = 0;
        for (int b = 0; b < Bc && b < 2048; b++) { g_off[b] = o; o += len[b]; }
    }
}

__global__ void out_kernel(const float* __restrict__ h, const float* __restrict__ fcW,
                           const float* __restrict__ fcb, const int* __restrict__ len,
                           float* __restrict__ out, int n_nodes, int Bc, int L, int TH,
                           int with_mask) {
    __shared__ float hsh[HID];
    int row = blockIdx.x;
    int b = row / L, j = row - b * L;
    int lenb = len[b];
    int m = (j < lenb) ? 1 : 0;
    if (with_mask && threadIdx.x == 0)
        out[(size_t)Bc * L * TH + row] = (float)m;
    size_t ro = (size_t)row * TH;
    if (!m) {
        for (int t = threadIdx.x; t < TH; t += blockDim.x) out[ro + t] = 0.f;
        return;
    }
    int node = g_off[b] + j;
    if (node >= n_nodes) node = n_nodes - 1;
    if (node < 0) node = 0;
    if (threadIdx.x < HID) hsh[threadIdx.x] = h[(size_t)node * HID + threadIdx.x];
    __syncthreads();
    for (int t = threadIdx.x; t < TH; t += blockDim.x) {
        float acc = fcb[t];
#pragma unroll
        for (int k = 0; k < HID; k++)
            acc = fmaf(hsh[k], __ldg(fcW + k * TH + t), acc);
        out[ro + t] = acc;
    }
}

// ---------------- host ----------------

extern "C" void kernel_launch(void* const* d_in, const int* in_sizes, int n_in,
                              void* d_out, int out_size) {
    const int*   an   = (const int*)d_in[0];
    const int*   src  = (const int*)d_in[1];
    const int*   dst  = (const int*)d_in[2];
    const int*   lsrc = (const int*)d_in[3];
    const int*   ldst = (const int*)d_in[4];
    const float* dist = (const float*)d_in[5];
    const float* ang  = (const float*)d_in[6];
    const int*   clen = (const int*)d_in[7];
    const float* emb  = (const float*)d_in[8];
    const float* eW   = (const float*)d_in[9];
    const float* eb   = (const float*)d_in[10];
    const float* aW   = (const float*)d_in[11];
    const float* ab   = (const float*)d_in[12];
    const float* Wg   = (const float*)d_in[13];
    const float* bg   = (const float*)d_in[14];
    const float* fcW  = (const float*)d_in[15];
    const float* fcb  = (const float*)d_in[16];

    int n_nodes = in_sizes[0];
    int n_edges = in_sizes[1];
    int n_lg    = in_sizes[3];
    int Bc      = in_sizes[7];
    int rbf_d   = in_sizes[9] / HID;
    int rbf_t   = in_sizes[11] / HID;
    int TH      = in_sizes[15] / HID;

    float *p_h, *p_e, *p_l, *p_C;
    cudaGetSymbolAddress((void**)&p_h, g_h);
    cudaGetSymbolAddress((void**)&p_e, g_e);
    cudaGetSymbolAddress((void**)&p_l, g_l);
    cudaGetSymbolAddress((void**)&p_C, g_C);

    static int attr_done = 0;
    (void)attr_done;
    cudaFuncSetAttribute(gemm4_kernel, cudaFuncAttributeMaxDynamicSharedMemorySize, 98304);
    cudaFuncSetAttribute(gemm1_kernel, cudaFuncAttributeMaxDynamicSharedMemorySize, 81920);

    long long per = (long long)out_size / Bc;
    int L, with_mask;
    if (per % (TH + 1) == 0) { L = (int)(per / (TH + 1)); with_mask = 1; }
    else                     { L = (int)(per / TH);       with_mask = 0; }

    const int GS = 148 * 8;

    embed_kernel<<<(n_nodes * HID + 255) / 256, 256>>>(an, emb, n_nodes);
    rbf_kernel<<<GS, 256>>>(dist, eW, eb, p_e, n_edges, rbf_d,
                            0.f, 8.f / (rbf_d - 1), (rbf_d - 1) / 8.f);
    rbf_kernel<<<GS, 256>>>(ang, aW, ab, p_l, n_lg, rbf_t,
                            -1.f, 2.f / (rbf_t - 1), (rbf_t - 1) / 2.f);

    struct GcnArgs { const int* s; const int* d; int n; int E; float* hb; float* ebuf; int layer; int we; };
    GcnArgs seq[6] = {
        { src,  dst,  n_nodes, n_edges, p_h, p_e, 0, 1 },
        { lsrc, ldst, n_edges, n_lg,    p_e, p_l, 1, 1 },
        { src,  dst,  n_nodes, n_edges, p_h, p_e, 2, 1 },
        { lsrc, ldst, n_edges, n_lg,    p_e, p_l, 3, 1 },
        { src,  dst,  n_nodes, n_edges, p_h, p_e, 4, 0 },
        { src,  dst,  n_nodes, n_edges, p_h, p_e, 5, 0 },
    };
    for (int i = 0; i < 6; i++) {
        const GcnArgs& a = seq[i];
        const float* Wl = Wg + (size_t)a.layer * 5 * 4096;
        const float* bl = bg + (size_t)a.layer * 5 * 64;
        int tiles4 = (a.n + 127) / 128;
        int tiles1 = (a.E + 255) / 256;
        gemm4_kernel<<<min(GS, tiles4), 256, 98304>>>(a.hb, Wl, bl, a.n);
        gemm1_kernel<<<min(GS, tiles1), 256, 81920>>>(a.ebuf, Wl + 2 * 4096, bl + 2 * 64, p_C, a.E);
        edge2_kernel<<<GS, 256>>>(a.s, a.d, a.ebuf, a.E, a.we);
        node_kernel<<<(a.n * HID + 255) / 256, 256>>>(a.hb, a.n);
    }

    offsets_kernel<<<1, 32>>>(clen, Bc);
    out_kernel<<<Bc * L, 256>>>(p_h, fcW, fcb, clen, (float*)d_out,
                                n_nodes, Bc, L, TH, with_mask);
}

// round 6
// speedup vs baseline: 1.1799x; 1.1799x over previous
#include <cuda_runtime.h>

#define HID 64
#define MAXN 500000
#define MAXE 800000

typedef unsigned long long ull;
typedef unsigned int uint;

__device__ __forceinline__ ull pack2(float lo, float hi) {
    ull r; asm("mov.b64 %0, {%1,%2};" : "=l"(r) : "f"(lo), "f"(hi)); return r;
}
__device__ __forceinline__ void fma2(ull& d, ull a, ull b) {
    asm("fma.rn.f32x2 %0, %1, %2, %0;" : "+l"(d) : "l"(a), "l"(b));
}
// split floats x0,x1 into bf16 hi word + bf16 lo word (low16=x0, high16=x1)
__device__ __forceinline__ void split2(float x0, float x1, uint& hw, uint& lw) {
    asm("cvt.rn.bf16x2.f32 %0, %1, %2;" : "=r"(hw) : "f"(x1), "f"(x0));
    float h0 = __uint_as_float(hw << 16);
    float h1 = __uint_as_float(hw & 0xFFFF0000u);
    float l0 = x0 - h0, l1 = x1 - h1;
    asm("cvt.rn.bf16x2.f32 %0, %1, %2;" : "=r"(lw) : "f"(l1), "f"(l0));
}
__device__ __forceinline__ uint smem_u32(const void* p) {
    uint a;
    asm("{ .reg .u64 t; cvta.to.shared.u64 t, %1; cvt.u32.u64 %0, t; }" : "=r"(a) : "l"(p));
    return a;
}
__device__ __forceinline__ void ldm4(uint* r, uint a) {
    asm volatile("ldmatrix.sync.aligned.m8n8.x4.shared.b16 {%0,%1,%2,%3}, [%4];"
                 : "=r"(r[0]), "=r"(r[1]), "=r"(r[2]), "=r"(r[3]) : "r"(a));
}
__device__ __forceinline__ void mma16816(float* c, const uint* a, uint b0, uint b1) {
    asm volatile("mma.sync.aligned.m16n8k16.row.col.f32.bf16.bf16.f32 "
                 "{%0,%1,%2,%3}, {%4,%5,%6,%7}, {%8,%9}, {%0,%1,%2,%3};"
                 : "+f"(c[0]), "+f"(c[1]), "+f"(c[2]), "+f"(c[3])
                 : "r"(a[0]), "r"(a[1]), "r"(a[2]), "r"(a[3]), "r"(b0), "r"(b1));
}

// ---------------- scratch ----------------
__device__ float g_h[50000 * HID];
__device__ float g_e[500000 * HID];
__device__ float g_l[800000 * HID];
__device__ float g_A[MAXN * HID];
__device__ float g_B[MAXN * HID];
__device__ float g_D[MAXN * HID];
__device__ float g_E[MAXN * HID];
__device__ float g_C[MAXE * HID];
__device__ float g_accsh[MAXN * HID];
__device__ float g_accs[MAXN * HID];
__device__ int   g_off[2048];

// ---------------- misc kernels ----------------

__global__ void embed_kernel(const int* __restrict__ an,
                             const float* __restrict__ emb, int n) {
    int i = blockIdx.x * blockDim.x + threadIdx.x;
    if (i < n * HID) g_h[i] = emb[an[i >> 6] * HID + (i & 63)];
}

__global__ void rbf_kernel(const float* __restrict__ x, const float* __restrict__ W,
                           const float* __restrict__ bias, float* __restrict__ out,
                           int n, int bins, float vmin, float step, float gamma) {
    __shared__ float phi[8 * 80];
    __shared__ float xs[8];
    int tx = threadIdx.x & 31, ez = threadIdx.x >> 5;
    ull bp = *(const ull*)(bias + 2 * tx);
    for (int base = blockIdx.x * 8; base < n; base += gridDim.x * 8) {
        __syncthreads();
        if (threadIdx.x < 8)
            xs[threadIdx.x] = (base + threadIdx.x < n) ? x[base + threadIdx.x] : 0.f;
        __syncthreads();
        for (int idx = threadIdx.x; idx < 8 * bins; idx += 256) {
            int ee = idx / bins, k = idx - ee * bins;
            float dd = xs[ee] - (vmin + k * step);
            phi[idx] = __expf(-gamma * dd * dd);
        }
        __syncthreads();
        int eid = base + ez;
        if (eid < n) {
            ull acc = bp;
            for (int k = 0; k < bins; k++) {
                float p = phi[ez * bins + k];
                fma2(acc, pack2(p, p), __ldg((const ull*)(W + k * HID + 2 * tx)));
            }
            *(ull*)(out + (size_t)eid * HID + 2 * tx) = acc;
        }
    }
}

__global__ void edge2_kernel(const int* __restrict__ src, const int* __restrict__ dst,
                             float* __restrict__ e, int E, int write_e) {
    int tx = threadIdx.x & 31;
    int gw = (blockIdx.x * blockDim.x + threadIdx.x) >> 5;
    int nw = (gridDim.x * blockDim.x) >> 5;
    for (int eid = gw; eid < E; eid += nw) {
        int s = __ldg(src + eid);
        int d = __ldg(dst + eid);
        size_t eo = (size_t)eid * 64 + 2 * tx;
        size_t so = (size_t)s * 64 + 2 * tx;
        size_t dofs = (size_t)d * 64 + 2 * tx;
        float2 ce = __ldg((const float2*)(g_C + eo));
        float2 dh = __ldg((const float2*)(g_D + so));
        float2 eh = __ldg((const float2*)(g_E + dofs));
        float2 bh = __ldg((const float2*)(g_B + so));
        float en0 = dh.x + eh.x + ce.x;
        float en1 = dh.y + eh.y + ce.y;
        float sg0 = 1.f / (1.f + __expf(-en0));
        float sg1 = 1.f / (1.f + __expf(-en1));
        atomicAdd(g_accsh + dofs,     bh.x * sg0);
        atomicAdd(g_accsh + dofs + 1, bh.y * sg1);
        atomicAdd(g_accs + dofs,      sg0);
        atomicAdd(g_accs + dofs + 1,  sg1);
        if (write_e) {
            float2 ev = *(const float2*)(e + eo);
            ev.x += en0 * sg0;
            ev.y += en1 * sg1;
            *(float2*)(e + eo) = ev;
        }
    }
}

__global__ void node_kernel(float* __restrict__ h, int n) {
    int i = blockIdx.x * blockDim.x + threadIdx.x;
    if (i < n * HID) {
        float hn = g_A[i] + g_accsh[i] / (g_accs[i] + 1e-6f);
        h[i] += hn / (1.f + __expf(-hn));
    }
}

__global__ void offsets_kernel(const int* __restrict__ len, int Bc) {
    if (threadIdx.x == 0 && blockIdx.x == 0) {
        int o = 0;
        for (int b = 0; b < Bc && b < 2048; b++) { g_off[b] = o; o += len[b]; }
    }
}

__global__ void out_kernel(const float* __restrict__ h, const float* __restrict__ fcW,
                           const float* __restrict__ fcb, const int* __restrict__ len,
                           float* __restrict__ out, int n_nodes, int Bc, int L, int TH,
                           int with_mask) {
    __shared__ float hsh[HID];
    int row = blockIdx.x;
    int b = row / L, j = row - b * L;
    int lenb = len[b];
    int m = (j < lenb) ? 1 : 0;
    if (with_mask && threadIdx.x == 0)
        out[(size_t)Bc * L * TH + row] = (float)m;
    size_t ro = (size_t)row * TH;
    if (!m) {
        for (int t = threadIdx.x; t < TH; t += blockDim.x) out[ro + t] = 0.f;
        return;
    }
    int node = g_off[b] + j;
    if (node >= n_nodes) node = n_nodes - 1;
    if (node < 0) node = 0;
    if (threadIdx.x < HID) hsh[threadIdx.x] = h[(size_t)node * HID + threadIdx.x];
    __syncthreads();
    for (int t = threadIdx.x; t < TH; t += blockDim.x) {
        float acc = fcb[t];
#pragma unroll
        for (int k = 0; k < HID; k++)
            acc = fmaf(hsh[k], __ldg(fcW + k * TH + t), acc);
        out[ro + t] = acc;
    }
}

// ---------------- HMMA (mma.sync bf16, 3-term split) GEMM ----------------
// nmat=4: o0..o3 = x @ W{0,1,3,4} + b  (zacc also zeroes g_accsh/g_accs)
// nmat=1: o0 = x @ W2 + b2
// smem row layout (stride 272B): [hi plane 128B | lo plane 128B | pad 16B]
__global__ void __launch_bounds__(256) gemm_mma(
    const float* __restrict__ x, const float* __restrict__ Wf,
    const float* __restrict__ bf,
    float* o0, float* o1, float* o2, float* o3,
    int n, int nmat, int zacc) {
    extern __shared__ __align__(16) char sm[];
    const int A_OFF = 1024;
    const int B_OFF = A_OFF + 128 * 272;
    float* biass = (float*)sm;
    int tid = threadIdx.x, lane = tid & 31, wid = tid >> 5;
    int wr = wid >> 1, wc = wid & 1;
    float* outp[4] = {o0, o1, o2, o3};
    int msel[4];
    if (nmat == 4) { msel[0] = 0; msel[1] = 1; msel[2] = 3; msel[3] = 4; }
    else { msel[0] = 2; msel[1] = 2; msel[2] = 2; msel[3] = 2; }

    // stage weights: B[n][k] bf16 hi|lo, once per CTA
    for (int t = tid; t < nmat * 512; t += 256) {
        int m = t >> 9, r = t & 511, nn = r >> 3, q = r & 7;
        const float* Wm = Wf + msel[m] * 4096;
        uint hw[4], lw[4];
#pragma unroll
        for (int i = 0; i < 4; i++) {
            int k = q * 8 + 2 * i;
            split2(__ldg(Wm + k * 64 + nn), __ldg(Wm + (k + 1) * 64 + nn), hw[i], lw[i]);
        }
        char* brow = sm + B_OFF + (m * 64 + nn) * 272;
        *(uint4*)(brow + q * 16) = make_uint4(hw[0], hw[1], hw[2], hw[3]);
        *(uint4*)(brow + 128 + q * 16) = make_uint4(lw[0], lw[1], lw[2], lw[3]);
    }
    for (int t = tid; t < nmat * 64; t += 256)
        biass[t] = bf[msel[t >> 6] * 64 + (t & 63)];

    // ldmatrix thread address bases
    uint aBase = smem_u32(sm + A_OFF) + (wr * 32 + (lane & 15)) * 272 + ((lane & 16) ? 16 : 0);
    uint bBase = smem_u32(sm + B_OFF) + (lane & 15) * 272 + ((lane & 16) ? 16 : 0);
    const int kA[12] = {0, 32, 64, 96, 0, 32, 64, 96, 128, 160, 192, 224};
    const int kB[12] = {0, 32, 64, 96, 128, 160, 192, 224, 0, 32, 64, 96};
    int cq = 2 * (lane & 3), rrow = lane >> 2;

    for (long long base = (long long)blockIdx.x * 128; base < n;
         base += (long long)gridDim.x * 128) {
        __syncthreads();
        // stage A tile (128 rows, bf16 hi|lo)
        for (int t = tid; t < 1024; t += 256) {
            int row = t >> 3, q = t & 7;
            long long gr = base + row;
            uint4 hv = make_uint4(0, 0, 0, 0), lv = hv;
            if (gr < n) {
                const float4* xp = (const float4*)(x + gr * 64 + q * 8);
                float4 p0 = __ldg(xp), p1 = __ldg(xp + 1);
                split2(p0.x, p0.y, hv.x, lv.x);
                split2(p0.z, p0.w, hv.y, lv.y);
                split2(p1.x, p1.y, hv.z, lv.z);
                split2(p1.z, p1.w, hv.w, lv.w);
            }
            char* arow = sm + A_OFF + row * 272;
            *(uint4*)(arow + q * 16) = hv;
            *(uint4*)(arow + 128 + q * 16) = lv;
        }
        if (zacc) {
            float4 z = make_float4(0.f, 0.f, 0.f, 0.f);
            for (int t = tid; t < 128 * 16; t += 256) {
                long long r = base + (t >> 4);
                if (r < n) {
                    int c = (t & 15) * 4;
                    *(float4*)(g_accsh + r * 64 + c) = z;
                    *(float4*)(g_accs + r * 64 + c) = z;
                }
            }
        }
        __syncthreads();

        for (int cb = 0; cb < nmat; cb++) {
            float c[2][4][4];
#pragma unroll
            for (int j = 0; j < 4; j++) {
                float b0v = biass[cb * 64 + wc * 32 + j * 8 + cq];
                float b1v = biass[cb * 64 + wc * 32 + j * 8 + cq + 1];
#pragma unroll
                for (int i = 0; i < 2; i++) {
                    c[i][j][0] = b0v; c[i][j][1] = b1v;
                    c[i][j][2] = b0v; c[i][j][3] = b1v;
                }
            }
            uint bMat = bBase + (cb * 64 + wc * 32) * 272;
#pragma unroll
            for (int v = 0; v < 12; v++) {
                uint af[2][4], bb[2][4];
                ldm4(af[0], aBase + kA[v]);
                ldm4(af[1], aBase + 16 * 272 + kA[v]);
                ldm4(bb[0], bMat + kB[v]);
                ldm4(bb[1], bMat + 16 * 272 + kB[v]);
#pragma unroll
                for (int i = 0; i < 2; i++) {
                    mma16816(c[i][0], af[i], bb[0][0], bb[0][2]);
                    mma16816(c[i][1], af[i], bb[0][1], bb[0][3]);
                    mma16816(c[i][2], af[i], bb[1][0], bb[1][2]);
                    mma16816(c[i][3], af[i], bb[1][1], bb[1][3]);
                }
            }
            float* op = outp[cb];
#pragma unroll
            for (int i = 0; i < 2; i++) {
                long long r0 = base + wr * 32 + i * 16 + rrow;
#pragma unroll
                for (int j = 0; j < 4; j++) {
                    int col = wc * 32 + j * 8 + cq;
                    if (r0 < n)
                        *(float2*)(op + r0 * 64 + col) = make_float2(c[i][j][0], c[i][j][1]);
                    if (r0 + 8 < n)
                        *(float2*)(op + (r0 + 8) * 64 + col) = make_float2(c[i][j][2], c[i][j][3]);
                }
            }
        }
    }
}

// ---------------- host ----------------

extern "C" void kernel_launch(void* const* d_in, const int* in_sizes, int n_in,
                              void* d_out, int out_size) {
    const int*   an   = (const int*)d_in[0];
    const int*   src  = (const int*)d_in[1];
    const int*   dst  = (const int*)d_in[2];
    const int*   lsrc = (const int*)d_in[3];
    const int*   ldst = (const int*)d_in[4];
    const float* dist = (const float*)d_in[5];
    const float* ang  = (const float*)d_in[6];
    const int*   clen = (const int*)d_in[7];
    const float* emb  = (const float*)d_in[8];
    const float* eW   = (const float*)d_in[9];
    const float* eb   = (const float*)d_in[10];
    const float* aW   = (const float*)d_in[11];
    const float* ab   = (const float*)d_in[12];
    const float* Wg   = (const float*)d_in[13];
    const float* bg   = (const float*)d_in[14];
    const float* fcW  = (const float*)d_in[15];
    const float* fcb  = (const float*)d_in[16];

    int n_nodes = in_sizes[0];
    int n_edges = in_sizes[1];
    int n_lg    = in_sizes[3];
    int Bc      = in_sizes[7];
    int rbf_d   = in_sizes[9] / HID;
    int rbf_t   = in_sizes[11] / HID;
    int TH      = in_sizes[15] / HID;

    float *p_h, *p_e, *p_l, *p_C, *p_A, *p_B, *p_D, *p_E;
    cudaGetSymbolAddress((void**)&p_h, g_h);
    cudaGetSymbolAddress((void**)&p_e, g_e);
    cudaGetSymbolAddress((void**)&p_l, g_l);
    cudaGetSymbolAddress((void**)&p_C, g_C);
    cudaGetSymbolAddress((void**)&p_A, g_A);
    cudaGetSymbolAddress((void**)&p_B, g_B);
    cudaGetSymbolAddress((void**)&p_D, g_D);
    cudaGetSymbolAddress((void**)&p_E, g_E);

    const int SM_MODE0 = 1024 + 128 * 272 + 4 * 64 * 272;  // 105472
    const int SM_MODE1 = 1024 + 128 * 272 + 1 * 64 * 272;  // 53248
    cudaFuncSetAttribute(gemm_mma, cudaFuncAttributeMaxDynamicSharedMemorySize, SM_MODE0);

    long long per = (long long)out_size / Bc;
    int L, with_mask;
    if (per % (TH + 1) == 0) { L = (int)(per / (TH + 1)); with_mask = 1; }
    else                     { L = (int)(per / TH);       with_mask = 0; }

    const int GS = 148 * 8;

    embed_kernel<<<(n_nodes * HID + 255) / 256, 256>>>(an, emb, n_nodes);
    rbf_kernel<<<GS, 256>>>(dist, eW, eb, p_e, n_edges, rbf_d,
                            0.f, 8.f / (rbf_d - 1), (rbf_d - 1) / 8.f);
    rbf_kernel<<<GS, 256>>>(ang, aW, ab, p_l, n_lg, rbf_t,
                            -1.f, 2.f / (rbf_t - 1), (rbf_t - 1) / 2.f);

    struct GcnArgs { const int* s; const int* d; int n; int E; float* hb; float* ebuf; int layer; int we; };
    GcnArgs seq[6] = {
        { src,  dst,  n_nodes, n_edges, p_h, p_e, 0, 1 },
        { lsrc, ldst, n_edges, n_lg,    p_e, p_l, 1, 1 },
        { src,  dst,  n_nodes, n_edges, p_h, p_e, 2, 1 },
        { lsrc, ldst, n_edges, n_lg,    p_e, p_l, 3, 1 },
        { src,  dst,  n_nodes, n_edges, p_h, p_e, 4, 0 },
        { src,  dst,  n_nodes, n_edges, p_h, p_e, 5, 0 },
    };
    for (int i = 0; i < 6; i++) {
        const GcnArgs& a = seq[i];
        const float* Wl = Wg + (size_t)a.layer * 5 * 4096;
        const float* bl = bg + (size_t)a.layer * 5 * 64;
        int t4 = (a.n + 127) / 128;
        int t1 = (a.E + 127) / 128;
        gemm_mma<<<min(296, t4), 256, SM_MODE0>>>(a.hb, Wl, bl,
                                                  p_A, p_B, p_D, p_E, a.n, 4, 1);
        gemm_mma<<<min(592, t1), 256, SM_MODE1>>>(a.ebuf, Wl, bl,
                                                  p_C, 0, 0, 0, a.E, 1, 0);
        edge2_kernel<<<GS, 256>>>(a.s, a.d, a.ebuf, a.E, a.we);
        node_kernel<<<(a.n * HID + 255) / 256, 256>>>(a.hb, a.n);
    }

    offsets_kernel<<<1, 32>>>(clen, Bc);
    out_kernel<<<Bc * L, 256>>>(p_h, fcW, fcb, clen, (float*)d_out,
                                n_nodes, Bc, L, TH, with_mask);
}